// round 16
// baseline (speedup 1.0000x reference)
#include <cuda_runtime.h>
#include <cuda_fp16.h>
#include <cstdint>
#include <cstring>

#define BB 4
#define CC 256
#define HH 180
#define WW 320
#define DD 64
#define HW (HH * WW)

#define XT 128            // M tile (x per CTA)
#define NXT 3             // ceil(320/128)
#define NTILES (NXT * HH * BB)   // 2160
#define KC 32             // channels per chunk
#define NCHUNK 8          // CC / KC
#define NSTAGE 3          // ring stages
#define NTHREADS 384      // warps 0-7 compute, 8-11 produce
#define GRIDX 304         // 152 SMs x 2 CTAs, persistent

// fp16 ring stage layout (padded rows, conflict-free ldmatrix)
#define SA_STRIDE 272     // 128 halfs + 16B pad
#define SB_STRIDE 400     // 192 halfs + 16B pad
#define SA16 (KC * SA_STRIDE)    // 8704
#define SB16 (KC * SB_STRIDE)    // 12800
#define STAGEB (SA16 + SB16)     // 21504
#define RING (NSTAGE * STAGEB)   // 64512
#define SOUT_OFF RING
#define SOUT_STRIDE 132
#define SMEM_TOTAL (RING + DD * SOUT_STRIDE * 4)   // 98304

static __device__ __forceinline__ uint32_t smem_u32(const void* p) {
    uint32_t a;
    asm("{ .reg .u64 t; cvta.to.shared.u64 t, %1; cvt.u32.u64 %0, t; }"
        : "=r"(a) : "l"(p));
    return a;
}

static __device__ __forceinline__ void mbar_init(uint32_t m, uint32_t cnt) {
    asm volatile("mbarrier.init.shared.b64 [%0], %1;" :: "r"(m), "r"(cnt) : "memory");
}
static __device__ __forceinline__ void mbar_arrive(uint32_t m) {
    asm volatile("mbarrier.arrive.shared.b64 _, [%0];" :: "r"(m) : "memory");
}
static __device__ __forceinline__ void mbar_wait(uint32_t m, uint32_t parity) {
    uint32_t done;
    asm volatile("{\n\t.reg .pred p;\n\t"
                 "mbarrier.try_wait.parity.acquire.cta.shared::cta.b64 p, [%1], %2;\n\t"
                 "selp.b32 %0, 1, 0, p;\n\t}"
                 : "=r"(done) : "r"(m), "r"(parity) : "memory");
    while (!done) {
        asm volatile("{\n\t.reg .pred p;\n\t"
                     "mbarrier.try_wait.parity.acquire.cta.shared::cta.b64 p, [%1], %2, 0x989680;\n\t"
                     "selp.b32 %0, 1, 0, p;\n\t}"
                     : "=r"(done) : "r"(m), "r"(parity) : "memory");
    }
}

static __device__ __forceinline__ void ldsm4t(uint32_t& r0, uint32_t& r1,
                                              uint32_t& r2, uint32_t& r3,
                                              uint32_t addr) {
    asm volatile("ldmatrix.sync.aligned.m8n8.x4.trans.shared.b16 {%0,%1,%2,%3}, [%4];"
                 : "=r"(r0), "=r"(r1), "=r"(r2), "=r"(r3) : "r"(addr));
}

static __device__ __forceinline__ void mma16816(float* c,
                                                uint32_t a0, uint32_t a1,
                                                uint32_t a2, uint32_t a3,
                                                uint32_t b0, uint32_t b1) {
    asm volatile("mma.sync.aligned.m16n8k16.row.col.f32.f16.f16.f32 "
                 "{%0,%1,%2,%3},{%4,%5,%6,%7},{%8,%9},{%0,%1,%2,%3};"
                 : "+f"(c[0]), "+f"(c[1]), "+f"(c[2]), "+f"(c[3])
                 : "r"(a0), "r"(a1), "r"(a2), "r"(a3), "r"(b0), "r"(b1));
}

static __device__ __forceinline__ uint32_t pack_h2(float x, float y) {
    __half2 h = __floats2half2_rn(x, y);
    uint32_t u;
    memcpy(&u, &h, 4);
    return u;
}

__global__ __launch_bounds__(NTHREADS, 2)
void cost_volume_ws(const float* __restrict__ Lp,
                    const float* __restrict__ Rp,
                    float* __restrict__ out) {
    extern __shared__ __align__(16) char dyn[];
    __shared__ __align__(8) unsigned long long s_mb[2 * NSTAGE];  // full[3], empty[3]

    const uint32_t base = smem_u32(dyn);
    const uint32_t mb = smem_u32(s_mb);
    const int tid = threadIdx.x;
    const int wid = tid >> 5;
    const int lid = tid & 31;
    const int bid = blockIdx.x;

    if (tid == 0) {
#pragma unroll
        for (int i = 0; i < NSTAGE; ++i) {
            mbar_init(mb + i * 8, 128);                 // full[i]: 128 producers
            mbar_init(mb + (NSTAGE + i) * 8, 256);      // empty[i]: 256 consumers
        }
    }
    __syncthreads();

    const int myTiles = (NTILES - 1 - bid) / GRIDX + 1;
    const int gEnd = myTiles * NCHUNK;

    if (wid >= 8) {
        // ================= PRODUCER (warps 8-11, 128 threads) =================
        const int pt = tid - 256;            // 0..127
        const int prow = pt >> 2;            // 0..31 (c-row within chunk)
        const int pq = pt & 3;
        const size_t prowHW = (size_t)prow * HW;
        // smem store bases (stage-relative)
        const int a_sts = prow * SA_STRIDE + 64 * pq;      // + 8p
        const int b_sts = prow * SB_STRIDE + 96 * pq;      // + 8p
        const int a_colbase = 32 * pq;                     // + 4p (floats)
        const int b_colbase = 48 * pq;                     // + 4p (floats)
        const float4 zero4 = make_float4(0.f, 0.f, 0.f, 0.f);

        const float* Lt = nullptr;
        const float* Rt = nullptr;
        bool a_ok = false;
        int y_lo = 0;

        int s = 0, cyc = 0;
#pragma unroll 1
        for (int g = 0; g < gEnd; ++g) {
            const int cc = g & (NCHUNK - 1);
            if (cc == 0) {
                const int tile = bid + (g >> 3) * GRIDX;
                const int xtile = tile % NXT;
                const int hh = (tile / NXT) % HH;
                const int bb = tile / (NXT * HH);
                const int x0 = xtile * XT;
                Lt = Lp + (size_t)bb * CC * HW + (size_t)hh * WW + x0 + a_colbase;
                Rt = Rp + (size_t)bb * CC * HW + (size_t)hh * WW;
                a_ok = (x0 + a_colbase) < WW;   // WW multiple of 32 -> uniform
                y_lo = x0 - 64 + b_colbase;
            }
            if (g >= NSTAGE) mbar_wait(mb + (NSTAGE + s) * 8, (cyc - 1) & 1);

            const size_t coff = (size_t)cc * KC * HW + prowHW;
            const float* La = Lt + coff;
            const float* Rb = Rt + coff;
            char* sA = dyn + s * STAGEB + a_sts;
            char* sB = dyn + s * STAGEB + SA16 + b_sts;
#pragma unroll
            for (int p = 0; p < 8; ++p) {
                float4 v = a_ok ? *(const float4*)(La + 4 * p) : zero4;
                uint2 u;
                u.x = pack_h2(v.x, v.y);
                u.y = pack_h2(v.z, v.w);
                *(uint2*)(sA + 8 * p) = u;
            }
#pragma unroll
            for (int p = 0; p < 12; ++p) {
                const int y = y_lo + 4 * p;
                float4 v = ((unsigned)y <= (WW - 4)) ? *(const float4*)(Rb + y)
                                                     : zero4;
                uint2 u;
                u.x = pack_h2(v.x, v.y);
                u.y = pack_h2(v.z, v.w);
                *(uint2*)(sB + 8 * p) = u;
            }
            mbar_arrive(mb + s * 8);   // full[s]
            if (++s == NSTAGE) { s = 0; ++cyc; }
        }
    } else {
        // ================= CONSUMER (warps 0-7, 256 threads) =================
        const uint32_t a_loff =
            (uint32_t)(((lid & 7) + ((lid >> 4) & 1) * 8) * SA_STRIDE +
                       (16 * wid + ((lid >> 3) & 1) * 8) * 2);
        const uint32_t b_loff =
            (uint32_t)(((lid & 7) + ((lid >> 3) & 1) * 8) * SB_STRIDE +
                       (16 * wid + ((lid >> 4) & 1) * 8) * 2);

        float acc[10][4];
        int s = 0, cyc = 0;
#pragma unroll 1
        for (int g = 0; g < gEnd; ++g) {
            const int cc = g & (NCHUNK - 1);
            if (cc == 0) {
#pragma unroll
                for (int t = 0; t < 10; ++t)
#pragma unroll
                    for (int j = 0; j < 4; ++j) acc[t][j] = 0.0f;
            }

            mbar_wait(mb + s * 8, cyc & 1);   // full[s]
            {
                const uint32_t abase = base + (uint32_t)(s * STAGEB) + a_loff;
                const uint32_t bbase =
                    base + (uint32_t)(s * STAGEB + SA16) + b_loff;
#pragma unroll
                for (int ks = 0; ks < 2; ++ks) {
                    uint32_t a0, a1, a2, a3;
                    ldsm4t(a0, a1, a2, a3,
                           abase + (uint32_t)(ks * 16 * SA_STRIDE));
#pragma unroll
                    for (int tp = 0; tp < 5; ++tp) {
                        uint32_t b0, b1, b2, b3;
                        ldsm4t(b0, b1, b2, b3,
                               bbase + (uint32_t)(ks * 16 * SB_STRIDE + tp * 32));
                        mma16816(acc[2 * tp],     a0, a1, a2, a3, b0, b1);
                        mma16816(acc[2 * tp + 1], a0, a1, a2, a3, b2, b3);
                    }
                }
            }
            mbar_arrive(mb + (NSTAGE + s) * 8);   // empty[s]
            if (++s == NSTAGE) { s = 0; ++cyc; }

            if (cc == NCHUNK - 1) {
                // ---- epilogue for tile g>>3 ----
                const int tile = bid + (g >> 3) * GRIDX;
                const int xtile = tile % NXT;
                const int hh = (tile / NXT) % HH;
                const int bb = tile / (NXT * HH);
                const int x0 = xtile * XT;

                float* sOut = (float*)(dyn + SOUT_OFF);
                const float sc = 1.0f / 256.0f;
                const int gq = lid >> 2;
                const int tg = lid & 3;
#pragma unroll
                for (int t = 0; t < 10; ++t) {
#pragma unroll
                    for (int j = 0; j < 4; ++j) {
                        const int r = gq + (j >> 1) * 8;
                        const int cn = 2 * tg + (j & 1);
                        const int i = r + 64 - 8 * t - cn;
                        if (i >= 0 && i < DD)
                            sOut[i * SOUT_STRIDE + 16 * wid + r] = acc[t][j] * sc;
                    }
                }
                asm volatile("bar.sync 1, 256;" ::: "memory");
                {
                    const int xl4 = lid * 4;
                    if (x0 + xl4 < WW) {
#pragma unroll
                        for (int i = wid; i < DD; i += 8) {
                            float4 v = *(const float4*)&sOut[i * SOUT_STRIDE + xl4];
                            __stcs((float4*)&out[(((size_t)bb * DD + i) * HH + hh) *
                                                     WW + x0 + xl4], v);
                        }
                    }
                }
                asm volatile("bar.sync 1, 256;" ::: "memory");
            }
        }
    }
}

extern "C" void kernel_launch(void* const* d_in, const int* in_sizes, int n_in,
                              void* d_out, int out_size) {
    const float* left  = (const float*)d_in[0];
    const float* right = (const float*)d_in[1];
    float* out = (float*)d_out;
    (void)in_sizes; (void)n_in; (void)out_size;

    cudaFuncSetAttribute(cost_volume_ws,
                         cudaFuncAttributeMaxDynamicSharedMemorySize, SMEM_TOTAL);
    dim3 grid(GRIDX);
    dim3 block(NTHREADS);
    cost_volume_ws<<<grid, block, SMEM_TOTAL>>>(left, right, out);
}

// round 17
// speedup vs baseline: 1.7989x; 1.7989x over previous
#include <cuda_runtime.h>
#include <cuda_fp16.h>
#include <cstdint>
#include <cstring>

#define BB 4
#define CC 256
#define HH 180
#define WW 320
#define DD 64
#define HW (HH * WW)

#define XT 128           // M tile (x per CTA)
#define NXT 3            // ceil(320/128)
#define NTILES (NXT * HH * BB)  // 2160
#define KC 32            // channels per chunk
#define NCHUNK (CC / KC) // 8
#define NTHREADS 256     // 8 warps, warp w -> rows 16w..16w+15
#define GRIDX 304        // 152 SMs x 2 CTAs, persistent

// smem (bytes). k-major, 16B-padded rows for conflict-free ldmatrix
#define SA_STRIDE 272            // 128 halfs + pad = 17 * 16B
#define SB_STRIDE 400            // 192 halfs + pad = 25 * 16B
#define SA_BYTES (KC * SA_STRIDE)        // 8704
#define SB_BYTES (KC * SB_STRIDE)        // 12800
#define SB_BASE (2 * SA_BYTES)           // 17408
#define SMEM_BYTES (2 * SA_BYTES + 2 * SB_BYTES)  // 43008
#define SOUT_STRIDE 132          // floats; 64*132*4 = 33792 <= 43008

__device__ int g_tile_ctr;

__global__ void reset_ctr_kernel() { g_tile_ctr = GRIDX; }

static __device__ __forceinline__ uint32_t smem_u32(const void* p) {
    uint32_t a;
    asm("{ .reg .u64 t; cvta.to.shared.u64 t, %1; cvt.u32.u64 %0, t; }"
        : "=r"(a) : "l"(p));
    return a;
}

static __device__ __forceinline__ void ldsm4t(uint32_t& r0, uint32_t& r1,
                                              uint32_t& r2, uint32_t& r3,
                                              uint32_t addr) {
    asm volatile("ldmatrix.sync.aligned.m8n8.x4.trans.shared.b16 {%0,%1,%2,%3}, [%4];"
                 : "=r"(r0), "=r"(r1), "=r"(r2), "=r"(r3) : "r"(addr));
}

static __device__ __forceinline__ void mma16816(float* c,
                                                uint32_t a0, uint32_t a1,
                                                uint32_t a2, uint32_t a3,
                                                uint32_t b0, uint32_t b1) {
    asm volatile("mma.sync.aligned.m16n8k16.row.col.f32.f16.f16.f32 "
                 "{%0,%1,%2,%3},{%4,%5,%6,%7},{%8,%9},{%0,%1,%2,%3};"
                 : "+f"(c[0]), "+f"(c[1]), "+f"(c[2]), "+f"(c[3])
                 : "r"(a0), "r"(a1), "r"(a2), "r"(a3), "r"(b0), "r"(b1));
}

static __device__ __forceinline__ uint32_t pack_h2(float x, float y) {
    __half2 h = __floats2half2_rn(x, y);
    uint32_t u;
    memcpy(&u, &h, 4);
    return u;
}

__global__ __launch_bounds__(NTHREADS, 2)
void cost_volume_hmma(const float* __restrict__ Lp,
                      const float* __restrict__ Rp,
                      float* __restrict__ out) {
    __shared__ __align__(16) char sBuf[SMEM_BYTES];
    __shared__ int sNext;

    const int tid = threadIdx.x;
    const int wid = tid >> 5;
    const int lid = tid & 31;

    const uint32_t sbase = smem_u32(sBuf);

    // ---- per-thread loader constants (tile-invariant) ----
    // A: 32 c-rows x 32 quads (128 x) = 1024 quads, 4 per thread
    const int a_xq4 = (tid & 31) * 4;
    int a_cHW[4];
#pragma unroll
    for (int p = 0; p < 4; ++p) a_cHW[p] = ((tid + p * NTHREADS) >> 5) * HW;
    // B: 32 c-rows x 48 quads (192 y) = 1536 quads, 6 per thread
    const int b_cHW = (tid >> 3) * HW;
    int b_yq4[6];
#pragma unroll
    for (int p = 0; p < 6; ++p) b_yq4[p] = ((tid & 7) + p * 8) * 4;

    // smem store offsets (tile-invariant)
    int a_soff[4], b_soff[6];
#pragma unroll
    for (int p = 0; p < 4; ++p) {
        int q = tid + p * NTHREADS;
        a_soff[p] = (q >> 5) * SA_STRIDE + (q & 31) * 8;
    }
#pragma unroll
    for (int p = 0; p < 6; ++p)
        b_soff[p] = (tid >> 3) * SB_STRIDE + ((tid & 7) + p * 8) * 8;

    // ---- ldmatrix per-lane offsets ----
    const uint32_t a_loff =
        (uint32_t)(((lid & 7) + ((lid >> 4) & 1) * 8) * SA_STRIDE +
                   (16 * wid + ((lid >> 3) & 1) * 8) * 2);
    const uint32_t b_loff =
        (uint32_t)(((lid & 7) + ((lid >> 3) & 1) * 8) * SB_STRIDE +
                   (16 * wid + ((lid >> 4) & 1) * 8) * 2);

    float acc[10][4];
    float4 aq[4], bq[6];
    const float4 zero4 = make_float4(0.f, 0.f, 0.f, 0.f);

    auto ldg_chunk = [&](const float* Lc, const float* Rc, int x0v) {
        const int xx = x0v + a_xq4;
        const bool aok = xx < WW;
#pragma unroll
        for (int p = 0; p < 4; ++p)
            aq[p] = aok ? __ldcs((const float4*)(Lc + a_cHW[p] + xx)) : zero4;
#pragma unroll
        for (int p = 0; p < 6; ++p) {
            const int y = x0v - 64 + b_yq4[p];
            bq[p] = (y >= 0 && y < WW) ? *(const float4*)(Rc + b_cHW + y) : zero4;
        }
    };

    auto sts_chunk = [&](int buf) {
#pragma unroll
        for (int p = 0; p < 4; ++p) {
            uint2 u;
            u.x = pack_h2(aq[p].x, aq[p].y);
            u.y = pack_h2(aq[p].z, aq[p].w);
            *(uint2*)(sBuf + buf * SA_BYTES + a_soff[p]) = u;
        }
#pragma unroll
        for (int p = 0; p < 6; ++p) {
            uint2 u;
            u.x = pack_h2(bq[p].x, bq[p].y);
            u.y = pack_h2(bq[p].z, bq[p].w);
            *(uint2*)(sBuf + SB_BASE + buf * SB_BYTES + b_soff[p]) = u;
        }
    };

    auto compute = [&](int buf) {
        const uint32_t abase = sbase + (uint32_t)(buf * SA_BYTES) + a_loff;
        const uint32_t bbase = sbase + (uint32_t)(SB_BASE + buf * SB_BYTES) + b_loff;
#pragma unroll
        for (int ks = 0; ks < 2; ++ks) {
            uint32_t a0, a1, a2, a3;
            ldsm4t(a0, a1, a2, a3, abase + (uint32_t)(ks * 16 * SA_STRIDE));
#pragma unroll
            for (int tp = 0; tp < 5; ++tp) {
                uint32_t b0, b1, b2, b3;
                ldsm4t(b0, b1, b2, b3,
                       bbase + (uint32_t)(ks * 16 * SB_STRIDE + tp * 32));
                mma16816(acc[2 * tp],     a0, a1, a2, a3, b0, b1);
                mma16816(acc[2 * tp + 1], a0, a1, a2, a3, b2, b3);
            }
        }
    };

    // ---- persistent ticket loop ----
    int tile = blockIdx.x;   // first GRIDX tickets are implicit

    int xtile = tile % NXT;
    int hh = (tile / NXT) % HH;
    int bb = tile / (NXT * HH);
    int x0 = xtile * XT;
    const float* Lrow = Lp + (size_t)bb * CC * HW + (size_t)hh * WW;
    const float* Rrow = Rp + (size_t)bb * CC * HW + (size_t)hh * WW;

    // prologue: chunk 0 of first tile into registers
    ldg_chunk(Lrow, Rrow, x0);

    for (;;) {
        sts_chunk(0);
        if (tid == 0) sNext = atomicAdd(&g_tile_ctr, 1);   // grab next ticket
        __syncthreads();

        const int ntile = sNext;
        const bool have_next = ntile < NTILES;

#pragma unroll
        for (int t = 0; t < 10; ++t)
#pragma unroll
            for (int j = 0; j < 4; ++j) acc[t][j] = 0.0f;

        int nxtile = 0, nhh = 0, nbb = 0, nx0 = 0;
        const float *Lnrow = Lrow, *Rnrow = Rrow;
        if (have_next) {
            nxtile = ntile % NXT;
            nhh = (ntile / NXT) % HH;
            nbb = ntile / (NXT * HH);
            nx0 = nxtile * XT;
            Lnrow = Lp + (size_t)nbb * CC * HW + (size_t)nhh * WW;
            Rnrow = Rp + (size_t)nbb * CC * HW + (size_t)nhh * WW;
        }

        // ---- mainloop over K chunks, depth-1 register pipeline ----
#pragma unroll 1
        for (int k = 0; k < NCHUNK; ++k) {
            if (k + 1 < NCHUNK) {
                ldg_chunk(Lrow + (size_t)(k + 1) * KC * HW,
                          Rrow + (size_t)(k + 1) * KC * HW, x0);
            } else if (have_next) {
                ldg_chunk(Lnrow, Rnrow, nx0);   // cross-tile prefetch of chunk 0
            }
            compute(k & 1);
            if (k + 1 < NCHUNK) sts_chunk((k + 1) & 1);
            __syncthreads();
        }

        // ---- epilogue: diagonal remap into sOut[i][x], i = x - y ----
        float* sOut = (float*)sBuf;
        const float sc = 1.0f / 256.0f;
        const int g = lid >> 2;
        const int tg = lid & 3;
#pragma unroll
        for (int t = 0; t < 10; ++t) {
#pragma unroll
            for (int j = 0; j < 4; ++j) {
                const int r = g + (j >> 1) * 8;
                const int cn = 2 * tg + (j & 1);
                const int i = r + 64 - 8 * t - cn;   // disparity
                if (i >= 0 && i < DD)
                    sOut[i * SOUT_STRIDE + 16 * wid + r] = acc[t][j] * sc;
            }
        }
        __syncthreads();

        // ---- coalesced float4 streaming stores ----
        {
            const int xl4 = lid * 4;
            if (x0 + xl4 < WW) {
#pragma unroll
                for (int i = wid; i < DD; i += 8) {
                    float4 v = *(const float4*)&sOut[i * SOUT_STRIDE + xl4];
                    __stcs((float4*)&out[(((size_t)bb * DD + i) * HH + hh) * WW +
                                         x0 + xl4], v);
                }
            }
        }

        if (!have_next) break;
        __syncthreads();   // sOut reads done before next tile's sts overwrites

        tile = ntile;
        xtile = nxtile; hh = nhh; bb = nbb; x0 = nx0;
        Lrow = Lnrow; Rrow = Rnrow;
    }
}

extern "C" void kernel_launch(void* const* d_in, const int* in_sizes, int n_in,
                              void* d_out, int out_size) {
    const float* left  = (const float*)d_in[0];
    const float* right = (const float*)d_in[1];
    float* out = (float*)d_out;
    (void)in_sizes; (void)n_in; (void)out_size;

    reset_ctr_kernel<<<1, 1>>>();
    dim3 grid(GRIDX);          // persistent: 152 SMs x 2 CTAs, ticket-scheduled
    dim3 block(NTHREADS);
    cost_volume_hmma<<<grid, block>>>(left, right, out);
}